// round 9
// baseline (speedup 1.0000x reference)
#include <cuda_runtime.h>
#include <cstdint>

// Gent hyperelastic energy over N 3x3 deformation gradients (elementwise).
//   I1 = ||F||_F^2 ; J = det(F) ; I1bar = I1 * J^(-2/3)
//   vol = (J^2-1)/2 - ln J ;  w = A*ln(1 - (I1bar-3)/JM) + B*vol^4
//   A = -(G/2)*JM = -1442307.6923..., B = K/2 = 31250, JM = 100.
//
// Max CTA-level memory concurrency: 64 threads, 128 matrices/CTA = 4.5 KB
// smem -> 32 CTAs/SM (CTA cap) x 2 warps = 64 warps (full occupancy),
// ~32 independent TMA bulk fetches in flight per SM.
// Whole tile fetched by ONE cp.async.bulk + mbarrier; zero per-element
// load instructions. Partial last tile via clamped byte count (grid exact
// for N=4M anyway).
// Math: one MUFU.LG2 feeds ln(J) and J^(-2/3); ln(1-u) via 5-term series.
// Output: streaming stores (st.global.cs).

#define THREADS 64
#define MPT 2
#define TILE_MATS (THREADS * MPT)            // 128
#define TILE_F (TILE_MATS * 9)               // 1152 floats
#define TILE_BYTES (TILE_F * 4)              // 4608 bytes

__global__ __launch_bounds__(THREADS)
void gent_kernel(const float* __restrict__ x, float* __restrict__ w, int n)
{
    __shared__ alignas(128) float sx[TILE_F];
    __shared__ alignas(8) uint64_t mbar;

    const int tid = threadIdx.x;
    const size_t total_bytes = (size_t)n * 36u;
    const size_t base_bytes = (size_t)blockIdx.x * TILE_BYTES;

    uint32_t smem_dst = (uint32_t)__cvta_generic_to_shared(sx);
    uint32_t mbar_a = (uint32_t)__cvta_generic_to_shared(&mbar);

    if (tid == 0) {
        asm volatile("mbarrier.init.shared::cta.b64 [%0], 1;" :: "r"(mbar_a) : "memory");
    }
    __syncthreads();

    if (tid == 0) {
        size_t rem = total_bytes - base_bytes;
        uint32_t bytes = rem < (size_t)TILE_BYTES ? (uint32_t)rem : (uint32_t)TILE_BYTES;
        const char* gsrc = reinterpret_cast<const char*>(x) + base_bytes;
        asm volatile("mbarrier.arrive.expect_tx.shared::cta.b64 _, [%0], %1;"
                     :: "r"(mbar_a), "r"(bytes) : "memory");
        asm volatile("cp.async.bulk.shared::cta.global.mbarrier::complete_tx::bytes "
                     "[%0], [%1], %2, [%3];"
                     :: "r"(smem_dst), "l"(gsrc), "r"(bytes), "r"(mbar_a) : "memory");
    }

    // All threads wait for the bulk copy (phase 0).
    asm volatile(
        "{\n\t"
        ".reg .pred P;\n\t"
        "LAB_WAIT_%=:\n\t"
        "mbarrier.try_wait.parity.shared::cta.b64 P, [%0], 0, 0x989680;\n\t"
        "@P bra LAB_DONE_%=;\n\t"
        "bra LAB_WAIT_%=;\n\t"
        "LAB_DONE_%=:\n\t"
        "}"
        :: "r"(mbar_a) : "memory");

    const float A = -1442307.6923076923f;   // -(G/2)*JM
    const float B = 31250.0f;               // K/2
    const float JM_inv = 0.01f;
    const float LN2 = 0.69314718055994531f;

    const long long mat_base = (long long)blockIdx.x * TILE_MATS;

    #pragma unroll
    for (int m = 0; m < MPT; m++) {
        const int local = tid + m * THREADS;     // strided: conflict-free smem
        const long long gi = mat_base + local;
        if (gi < n) {
            const float* mm = &sx[local * 9];
            float a00 = mm[0], a01 = mm[1], a02 = mm[2];
            float a10 = mm[3], a11 = mm[4], a12 = mm[5];
            float a20 = mm[6], a21 = mm[7], a22 = mm[8];

            float I1 = a00*a00 + a01*a01 + a02*a02
                     + a10*a10 + a11*a11 + a12*a12
                     + a20*a20 + a21*a21 + a22*a22;

            float J = a00*(a11*a22 - a12*a21)
                    - a01*(a10*a22 - a12*a20)
                    + a02*(a10*a21 - a11*a20);

            // One LG2 feeds both ln(J) and J^(-2/3).
            float l2 = __log2f(J);
            float lnJ = l2 * LN2;
            float Jm23 = exp2f(-0.66666666666666667f * l2);

            float I1bar = I1 * Jm23;

            float vol = fmaf(0.5f, J*J, -0.5f) - lnJ;
            float vol2 = vol * vol;
            float vol4 = vol2 * vol2;

            // ln(1-u) = -(u + u^2/2 + u^3/3 + u^4/4 + u^5/5)
            float u = (I1bar - 3.0f) * JM_inv;
            float p = fmaf(u, 0.2f, 0.25f);
            p = fmaf(u, p, 0.33333333333333333f);
            p = fmaf(u, p, 0.5f);
            p = fmaf(u, p, 1.0f);
            float ln1mu = -u * p;

            float wv = fmaf(B, vol4, A * ln1mu);
            __stcs(&w[gi], wv);   // streaming store: don't pollute L2
        }
    }
}

extern "C" void kernel_launch(void* const* d_in, const int* in_sizes, int n_in,
                              void* d_out, int out_size)
{
    const float* x = (const float*)d_in[0];
    float* w = (float*)d_out;
    const int n = out_size;  // 4,000,000
    const int blocks = (n + TILE_MATS - 1) / TILE_MATS;  // 31250
    gent_kernel<<<blocks, THREADS>>>(x, w, n);
}

// round 11
// speedup vs baseline: 1.0115x; 1.0115x over previous
#include <cuda_runtime.h>
#include <cstdint>

// Gent hyperelastic energy over N 3x3 deformation gradients (elementwise).
//   I1 = ||F||_F^2 ; J = det(F) ; I1bar = I1 * J^(-2/3)
//   vol = (J^2-1)/2 - ln J ;  w = A*ln(1 - (I1bar-3)/JM) + B*vol^4
//   A = -(G/2)*JM = -1442307.6923..., B = K/2 = 31250, JM = 100.
//
// Best-dur configuration (R7): 128 threads, 256 matrices/CTA = 9 KB smem,
// grid 15625. Whole tile fetched by ONE cp.async.bulk (TMA) + mbarrier.
// NEW: TMA load carries an L2::evict_first cache policy — the 144 MB
// read-once stream shouldn't hold L2 residency against the write stream.
// Math: one MUFU.LG2 feeds ln(J) and J^(-2/3); ln(1-u) via 5-term series.
// Output: streaming stores (st.global.cs).

#define THREADS 128
#define MPT 2
#define TILE_MATS (THREADS * MPT)            // 256
#define TILE_F (TILE_MATS * 9)               // 2304 floats
#define TILE_BYTES (TILE_F * 4)              // 9216 bytes

__global__ __launch_bounds__(THREADS)
void gent_kernel(const float* __restrict__ x, float* __restrict__ w, int n)
{
    __shared__ alignas(128) float sx[TILE_F];
    __shared__ alignas(8) uint64_t mbar;

    const int tid = threadIdx.x;
    const size_t total_bytes = (size_t)n * 36u;
    const size_t base_bytes = (size_t)blockIdx.x * TILE_BYTES;

    uint32_t smem_dst = (uint32_t)__cvta_generic_to_shared(sx);
    uint32_t mbar_a = (uint32_t)__cvta_generic_to_shared(&mbar);

    if (tid == 0) {
        asm volatile("mbarrier.init.shared::cta.b64 [%0], 1;" :: "r"(mbar_a) : "memory");
    }
    __syncthreads();

    if (tid == 0) {
        size_t rem = total_bytes - base_bytes;
        uint32_t bytes = rem < (size_t)TILE_BYTES ? (uint32_t)rem : (uint32_t)TILE_BYTES;
        const char* gsrc = reinterpret_cast<const char*>(x) + base_bytes;
        uint64_t pol;
        asm volatile("createpolicy.fractional.L2::evict_first.b64 %0, 1.0;" : "=l"(pol));
        asm volatile("mbarrier.arrive.expect_tx.shared::cta.b64 _, [%0], %1;"
                     :: "r"(mbar_a), "r"(bytes) : "memory");
        asm volatile("cp.async.bulk.shared::cta.global.mbarrier::complete_tx::bytes"
                     ".L2::cache_hint [%0], [%1], %2, [%3], %4;"
                     :: "r"(smem_dst), "l"(gsrc), "r"(bytes), "r"(mbar_a), "l"(pol)
                     : "memory");
    }

    // All threads wait for the bulk copy (phase 0).
    asm volatile(
        "{\n\t"
        ".reg .pred P;\n\t"
        "LAB_WAIT_%=:\n\t"
        "mbarrier.try_wait.parity.shared::cta.b64 P, [%0], 0, 0x989680;\n\t"
        "@P bra LAB_DONE_%=;\n\t"
        "bra LAB_WAIT_%=;\n\t"
        "LAB_DONE_%=:\n\t"
        "}"
        :: "r"(mbar_a) : "memory");

    const float A = -1442307.6923076923f;   // -(G/2)*JM
    const float B = 31250.0f;               // K/2
    const float JM_inv = 0.01f;
    const float LN2 = 0.69314718055994531f;

    const long long mat_base = (long long)blockIdx.x * TILE_MATS;

    #pragma unroll
    for (int m = 0; m < MPT; m++) {
        const int local = tid + m * THREADS;     // strided: conflict-free smem
        const long long gi = mat_base + local;
        if (gi < n) {
            const float* mm = &sx[local * 9];
            float a00 = mm[0], a01 = mm[1], a02 = mm[2];
            float a10 = mm[3], a11 = mm[4], a12 = mm[5];
            float a20 = mm[6], a21 = mm[7], a22 = mm[8];

            float I1 = a00*a00 + a01*a01 + a02*a02
                     + a10*a10 + a11*a11 + a12*a12
                     + a20*a20 + a21*a21 + a22*a22;

            float J = a00*(a11*a22 - a12*a21)
                    - a01*(a10*a22 - a12*a20)
                    + a02*(a10*a21 - a11*a20);

            // One LG2 feeds both ln(J) and J^(-2/3).
            float l2 = __log2f(J);
            float lnJ = l2 * LN2;
            float Jm23 = exp2f(-0.66666666666666667f * l2);

            float I1bar = I1 * Jm23;

            float vol = fmaf(0.5f, J*J, -0.5f) - lnJ;
            float vol2 = vol * vol;
            float vol4 = vol2 * vol2;

            // ln(1-u) = -(u + u^2/2 + u^3/3 + u^4/4 + u^5/5)
            float u = (I1bar - 3.0f) * JM_inv;
            float p = fmaf(u, 0.2f, 0.25f);
            p = fmaf(u, p, 0.33333333333333333f);
            p = fmaf(u, p, 0.5f);
            p = fmaf(u, p, 1.0f);
            float ln1mu = -u * p;

            float wv = fmaf(B, vol4, A * ln1mu);
            __stcs(&w[gi], wv);   // streaming store: don't pollute L2
        }
    }
}

extern "C" void kernel_launch(void* const* d_in, const int* in_sizes, int n_in,
                              void* d_out, int out_size)
{
    const float* x = (const float*)d_in[0];
    float* w = (float*)d_out;
    const int n = out_size;  // 4,000,000
    const int blocks = (n + TILE_MATS - 1) / TILE_MATS;  // 15625
    gent_kernel<<<blocks, THREADS>>>(x, w, n);
}

// round 12
// speedup vs baseline: 1.0390x; 1.0272x over previous
#include <cuda_runtime.h>
#include <cstdint>

// Gent hyperelastic energy over N 3x3 deformation gradients (elementwise).
//   I1 = ||F||_F^2 ; J = det(F) ; I1bar = I1 * J^(-2/3)
//   vol = (J^2-1)/2 - ln J ;  w = A*ln(1 - (I1bar-3)/JM) + B*vol^4
//   A = -(G/2)*JM = -1442307.6923..., B = K/2 = 31250, JM = 100.
//
// R7 config (best dur): 128 threads, 256 matrices/CTA = 9 KB smem, grid 15625.
// NEW: tile split into two 4.6 KB halves, each with its own mbarrier.
// Both TMA bulk copies are issued immediately; compute on half 1 starts as
// soon as it lands, overlapping with half 2's fetch — de-correlates the
// fetch/compute phases so DRAM stays fed.
// Math: one MUFU.LG2 feeds ln(J) and J^(-2/3); ln(1-u) via 5-term series.
// Output: streaming stores (st.global.cs).

#define THREADS 128
#define MPT 2
#define TILE_MATS (THREADS * MPT)            // 256
#define TILE_F (TILE_MATS * 9)               // 2304 floats
#define TILE_BYTES (TILE_F * 4)              // 9216 bytes
#define HALF_BYTES (TILE_BYTES / 2)          // 4608 bytes = 128 matrices

__device__ __forceinline__ void mbar_wait_phase0(uint32_t mbar_a) {
    asm volatile(
        "{\n\t"
        ".reg .pred P;\n\t"
        "LAB_WAIT_%=:\n\t"
        "mbarrier.try_wait.parity.shared::cta.b64 P, [%0], 0, 0x989680;\n\t"
        "@P bra LAB_DONE_%=;\n\t"
        "bra LAB_WAIT_%=;\n\t"
        "LAB_DONE_%=:\n\t"
        "}"
        :: "r"(mbar_a) : "memory");
}

__global__ __launch_bounds__(THREADS)
void gent_kernel(const float* __restrict__ x, float* __restrict__ w, int n)
{
    __shared__ alignas(128) float sx[TILE_F];
    __shared__ alignas(8) uint64_t mbar[2];

    const int tid = threadIdx.x;
    const size_t total_bytes = (size_t)n * 36u;
    const size_t base_bytes = (size_t)blockIdx.x * TILE_BYTES;

    uint32_t smem_dst = (uint32_t)__cvta_generic_to_shared(sx);
    uint32_t mbar_a0 = (uint32_t)__cvta_generic_to_shared(&mbar[0]);
    uint32_t mbar_a1 = (uint32_t)__cvta_generic_to_shared(&mbar[1]);

    if (tid == 0) {
        asm volatile("mbarrier.init.shared::cta.b64 [%0], 1;" :: "r"(mbar_a0) : "memory");
        asm volatile("mbarrier.init.shared::cta.b64 [%0], 1;" :: "r"(mbar_a1) : "memory");
    }
    __syncthreads();

    if (tid == 0) {
        const char* gsrc = reinterpret_cast<const char*>(x) + base_bytes;
        size_t rem = total_bytes - base_bytes;

        // Half 1
        uint32_t b0 = rem < (size_t)HALF_BYTES ? (uint32_t)rem : (uint32_t)HALF_BYTES;
        asm volatile("mbarrier.arrive.expect_tx.shared::cta.b64 _, [%0], %1;"
                     :: "r"(mbar_a0), "r"(b0) : "memory");
        asm volatile("cp.async.bulk.shared::cta.global.mbarrier::complete_tx::bytes "
                     "[%0], [%1], %2, [%3];"
                     :: "r"(smem_dst), "l"(gsrc), "r"(b0), "r"(mbar_a0) : "memory");

        // Half 2 (issued immediately; in flight concurrently)
        size_t rem2 = rem > (size_t)HALF_BYTES ? rem - HALF_BYTES : 0;
        uint32_t b1 = rem2 < (size_t)HALF_BYTES ? (uint32_t)rem2 : (uint32_t)HALF_BYTES;
        asm volatile("mbarrier.arrive.expect_tx.shared::cta.b64 _, [%0], %1;"
                     :: "r"(mbar_a1), "r"(b1) : "memory");
        if (b1 > 0) {
            asm volatile("cp.async.bulk.shared::cta.global.mbarrier::complete_tx::bytes "
                         "[%0], [%1], %2, [%3];"
                         :: "r"(smem_dst + HALF_BYTES), "l"(gsrc + HALF_BYTES),
                            "r"(b1), "r"(mbar_a1) : "memory");
        }
    }

    const float A = -1442307.6923076923f;   // -(G/2)*JM
    const float B = 31250.0f;               // K/2
    const float JM_inv = 0.01f;
    const float LN2 = 0.69314718055994531f;

    const long long mat_base = (long long)blockIdx.x * TILE_MATS;

    // Half m becomes ready as its mbarrier flips; compute overlaps the
    // other half's in-flight fetch.
    #pragma unroll
    for (int m = 0; m < MPT; m++) {
        mbar_wait_phase0(m == 0 ? mbar_a0 : mbar_a1);

        const int local = tid + m * THREADS;     // half m = mats [m*128, m*128+127]
        const long long gi = mat_base + local;
        if (gi < n) {
            const float* mm = &sx[local * 9];
            float a00 = mm[0], a01 = mm[1], a02 = mm[2];
            float a10 = mm[3], a11 = mm[4], a12 = mm[5];
            float a20 = mm[6], a21 = mm[7], a22 = mm[8];

            float I1 = a00*a00 + a01*a01 + a02*a02
                     + a10*a10 + a11*a11 + a12*a12
                     + a20*a20 + a21*a21 + a22*a22;

            float J = a00*(a11*a22 - a12*a21)
                    - a01*(a10*a22 - a12*a20)
                    + a02*(a10*a21 - a11*a20);

            // One LG2 feeds both ln(J) and J^(-2/3).
            float l2 = __log2f(J);
            float lnJ = l2 * LN2;
            float Jm23 = exp2f(-0.66666666666666667f * l2);

            float I1bar = I1 * Jm23;

            float vol = fmaf(0.5f, J*J, -0.5f) - lnJ;
            float vol2 = vol * vol;
            float vol4 = vol2 * vol2;

            // ln(1-u) = -(u + u^2/2 + u^3/3 + u^4/4 + u^5/5)
            float u = (I1bar - 3.0f) * JM_inv;
            float p = fmaf(u, 0.2f, 0.25f);
            p = fmaf(u, p, 0.33333333333333333f);
            p = fmaf(u, p, 0.5f);
            p = fmaf(u, p, 1.0f);
            float ln1mu = -u * p;

            float wv = fmaf(B, vol4, A * ln1mu);
            __stcs(&w[gi], wv);   // streaming store: don't pollute L2
        }
    }
}

extern "C" void kernel_launch(void* const* d_in, const int* in_sizes, int n_in,
                              void* d_out, int out_size)
{
    const float* x = (const float*)d_in[0];
    float* w = (float*)d_out;
    const int n = out_size;  // 4,000,000
    const int blocks = (n + TILE_MATS - 1) / TILE_MATS;  // 15625 (exact)
    gent_kernel<<<blocks, THREADS>>>(x, w, n);
}